// round 17
// baseline (speedup 1.0000x reference)
#include <cuda_runtime.h>
#include <cuda_fp16.h>

#define GN     128
#define GMASK  127
#define NCELLS (GN * GN * GN)

// grid scratch: 8 fp16 feats per cell, 2x2x2-blocked layout:
// one 128B line holds the 8 records of a 2x2x2 cell block. 32 MB.
__device__ uint4 g_gridh[NCELLS];

__device__ __forceinline__ int blocked_nid(int x, int y, int z) {
    return (((x >> 1) << 15) | ((y >> 1) << 9) | ((z >> 1) << 3))
         | ((x & 1) << 2) | ((y & 1) << 1) | (z & 1);
}

__device__ __forceinline__ unsigned h2_to_u(__half2 h) {
    return *reinterpret_cast<unsigned*>(&h);
}
__device__ __forceinline__ __half2 u_to_h2(unsigned u) {
    return *reinterpret_cast<__half2*>(&u);
}

// ---------------- P2G: 8 lanes/point, 4 points/warp, blocked grid (measured ~32.7us) ------
// lane = p*8 + s;  s = node id: ox=bit2, oy=bit1, oz=bit0.
__global__ __launch_bounds__(256)
void p2g_h(const float* __restrict__ pos,
           const float4* __restrict__ feat4, int n) {
    int lane = threadIdx.x & 31;
    int warp = (blockIdx.x * blockDim.x + threadIdx.x) >> 5;
    int i = warp * 4 + (lane >> 3);
    if (i >= n) return;

    int s = lane & 7;
    int ox = (s >> 2) & 1, oy = (s >> 1) & 1, oz = s & 1;

    float rx = __ldg(&pos[3 * i + 0]) * (float)GN;
    float ry = __ldg(&pos[3 * i + 1]) * (float)GN;
    float rz = __ldg(&pos[3 * i + 2]) * (float)GN;
    int bx = (int)rx, by = (int)ry, bz = (int)rz;
    float fx = rx - (float)bx, fy = ry - (float)by, fz = rz - (float)bz;

    float w = (ox ? fx : 1.0f - fx) * (oy ? fy : 1.0f - fy) * (oz ? fz : 1.0f - fz);

    float4 f0 = __ldg(&feat4[2 * i + 0]);
    float4 f1 = __ldg(&feat4[2 * i + 1]);

    int nx = (bx + ox) & GMASK;
    int ny = (by + oy) & GMASK;
    int nz = (bz + oz) & GMASK;
    int nid = blocked_nid(nx, ny, nz);

    __half2 h01 = __floats2half2_rn(w * f0.x, w * f0.y);
    __half2 h23 = __floats2half2_rn(w * f0.z, w * f0.w);
    __half2 h45 = __floats2half2_rn(w * f1.x, w * f1.y);
    __half2 h67 = __floats2half2_rn(w * f1.z, w * f1.w);

    asm volatile(
        "red.global.add.noftz.v4.f16x2 [%0], {%1, %2, %3, %4};"
        :: "l"(&g_gridh[nid]),
           "r"(h2_to_u(h01)), "r"(h2_to_u(h23)),
           "r"(h2_to_u(h45)), "r"(h2_to_u(h67))
        : "memory");
}

// ---------------- G2P: 8 lanes/point, ONE LDG.128 per lane, 4 points/thread ---------------
// lane = g*8 + s;  s = node id (ox=bit2, oy=bit1, oz=bit0).  The 8 lanes of a point
// issue ONE load instruction covering the whole 2x2x2 window: E[3.375] lines/pt
// (1 line for 12.5% of points).  3-level halving butterfly in half2:
//   ox (xor4): 2 SHFL + 2 HADD2   -> comps ox*4 + {0..3}
//   oy (xor2): 1 SHFL + 1 HADD2   -> comps ox*4+oy*2 + {0,1}
//   oz (xor1): 1 SHFL + 1 HADD2   -> lane extracts comp ox*4+oy*2+oz
// Store: out[8i + comp], 32B contiguous per point.
__device__ __forceinline__ float g2p_pt(const uint4& rec, float w,
                                        bool sox, bool soy, bool soz) {
    __half2 wh = __half2half2(__float2half_rn(w));
    const __half2* h = reinterpret_cast<const __half2*>(&rec);
    __half2 v0 = __hmul2(h[0], wh);   // comps (0,1)
    __half2 v1 = __hmul2(h[1], wh);   // comps (2,3)
    __half2 v2 = __hmul2(h[2], wh);   // comps (4,5)
    __half2 v3 = __hmul2(h[3], wh);   // comps (6,7)

    unsigned t, r;
    // ox (xor 4): keep (v2,v3) if ox else (v0,v1)
    __half2 a0, a1;
    t = h2_to_u(sox ? v0 : v2);
    r = __shfl_xor_sync(0xffffffffu, t, 4);
    a0 = __hadd2(sox ? v2 : v0, u_to_h2(r));
    t = h2_to_u(sox ? v1 : v3);
    r = __shfl_xor_sync(0xffffffffu, t, 4);
    a1 = __hadd2(sox ? v3 : v1, u_to_h2(r));
    // lane holds comps ox*4 + {(0,1),(2,3)}

    // oy (xor 2): keep a1 if oy else a0
    t = h2_to_u(soy ? a0 : a1);
    r = __shfl_xor_sync(0xffffffffu, t, 2);
    __half2 b = __hadd2(soy ? a1 : a0, u_to_h2(r));
    // lane holds comps ox*4 + oy*2 + {0,1}

    // oz (xor 1): partner has same comp pair; sum, then extract half by oz
    t = h2_to_u(b);
    r = __shfl_xor_sync(0xffffffffu, t, 1);
    __half2 c = __hadd2(b, u_to_h2(r));

    return soz ? __high2float(c) : __low2float(c);
}

struct PtW { float w; int nid; };

__device__ __forceinline__ PtW g2p_setup_w(const float* __restrict__ pos, int i,
                                           int ox, int oy, int oz) {
    float rx = __ldg(&pos[3 * i + 0]) * (float)GN;
    float ry = __ldg(&pos[3 * i + 1]) * (float)GN;
    float rz = __ldg(&pos[3 * i + 2]) * (float)GN;
    int bx = (int)rx, by = (int)ry, bz = (int)rz;
    float fx = rx - (float)bx, fy = ry - (float)by, fz = rz - (float)bz;

    PtW c;
    c.w = (ox ? fx : 1.0f - fx) * (oy ? fy : 1.0f - fy) * (oz ? fz : 1.0f - fz);
    int nx = (bx + ox) & GMASK;
    int ny = (by + oy) & GMASK;
    int nz = (bz + oz) & GMASK;
    c.nid = blocked_nid(nx, ny, nz);
    return c;
}

__global__ __launch_bounds__(256, 4)
void g2p_w8(const float* __restrict__ pos,
            float* __restrict__ out, int n) {
    int lane = threadIdx.x & 31;
    int warp = (blockIdx.x * blockDim.x + threadIdx.x) >> 5;
    int g = lane >> 3;          // point group within warp (0..3)
    int s = lane & 7;           // node id
    int ox = (s >> 2) & 1, oy = (s >> 1) & 1, oz = s & 1;
    bool sox = ox != 0, soy = oy != 0, soz = oz != 0;

    int base = warp * 16 + g;
    int i0 = base, i1 = base + 4, i2 = base + 8, i3 = base + 12;
    bool a0 = i0 < n, a1 = i1 < n, a2 = i2 < n, a3 = i3 < n;
    int ic0 = a0 ? i0 : (n - 1), ic1 = a1 ? i1 : (n - 1);
    int ic2 = a2 ? i2 : (n - 1), ic3 = a3 ? i3 : (n - 1);

    PtW c0 = g2p_setup_w(pos, ic0, ox, oy, oz);
    PtW c1 = g2p_setup_w(pos, ic1, ox, oy, oz);
    PtW c2 = g2p_setup_w(pos, ic2, ox, oy, oz);
    PtW c3 = g2p_setup_w(pos, ic3, ox, oy, oz);

    // 4 independent LDG.128 — one per point, whole stencil window per instruction
    uint4 r0 = __ldg(&g_gridh[c0.nid]);
    uint4 r1 = __ldg(&g_gridh[c1.nid]);
    uint4 r2 = __ldg(&g_gridh[c2.nid]);
    uint4 r3 = __ldg(&g_gridh[c3.nid]);

    float f0 = g2p_pt(r0, c0.w, sox, soy, soz);
    float f1 = g2p_pt(r1, c1.w, sox, soy, soz);
    float f2 = g2p_pt(r2, c2.w, sox, soy, soz);
    float f3 = g2p_pt(r3, c3.w, sox, soy, soz);

    int comp = ox * 4 + oy * 2 + oz;
    if (a0) out[8 * (size_t)i0 + comp] = f0;
    if (a1) out[8 * (size_t)i1 + comp] = f1;
    if (a2) out[8 * (size_t)i2 + comp] = f2;
    if (a3) out[8 * (size_t)i3 + comp] = f3;
}

extern "C" void kernel_launch(void* const* d_in, const int* in_sizes, int n_in,
                              void* d_out, int out_size) {
    const float* pos  = (const float*)d_in[0];   // [N,3] f32
    const float* feat = (const float*)d_in[1];   // [N,8] f32
    float* out        = (float*)d_out;           // [N,8] f32
    int n = in_sizes[0] / 3;

    void* gptr = nullptr;
    cudaGetSymbolAddress(&gptr, g_gridh);
    cudaMemsetAsync(gptr, 0, (size_t)NCELLS * sizeof(uint4), 0);

    // p2g: 8 lanes/point -> 32 points per 256-thread block
    int pb = (n + 31) / 32;
    p2g_h<<<pb, 256>>>(pos, (const float4*)feat, n);

    // g2p: 8 lanes/point, 4 pts/thread -> 128 points per 256-thread block
    int gb = (n + 127) / 128;
    g2p_w8<<<gb, 256>>>(pos, (float*)out, n);
}